// round 16
// baseline (speedup 1.0000x reference)
#include <cuda_runtime.h>
#include <cstdint>

// Fixed problem shape
constexpr int B_   = 32;
constexpr int C_   = 256;
constexpr int N_   = 4608;          // 96*48
constexpr int TILE = 64;            // n per block
constexpr int NT   = N_ / TILE;     // 72 tiles per batch
constexpr int TPB  = 512;

// Shared-memory layout (floats)
constexpr int OFF_X   = 0;                 // 16384 : x tile [c][n]
constexpr int OFF_PD  = 16384;             // 1536  : pd g/t/p [8][64] each
//   aliases inside PD region (valid after the merge phase):
constexpr int OFF_SA  = OFF_PD;            // 256 : Ww*inv
constexpr int OFF_SD  = OFF_PD + 256;      // 256 : (Wb-mean)*inv+beta
constexpr int OFF_SPS = OFF_PD + 512;      // 72  : staged tile partials
constexpr int OFF_RED = OFF_PD + 600;      // 8   : pg warp partials
constexpr int OFF_W   = OFF_PD + 1536;     // 768 : g/theta/phi weights
constexpr int OFF_TH  = OFF_W + 768;       // 64  : theta row (16B aligned)
constexpr int SMEM_F  = OFF_TH + 64;       // 18752 floats
constexpr int SMEM_B  = SMEM_F * 4;        // 75008 bytes (3 blocks/SM)

// Counter padding: one 128-byte L2 line per batch (no false sharing)
constexpr int CPAD = 32;

// Scratch (__device__ globals: allocation-free rule; zero-initialized)
__device__ float    g_sp[B_ * NT];
__device__ unsigned g_cnt[B_ * CPAD];
__device__ unsigned g_done[B_ * CPAD];

__device__ __forceinline__ void cp_async16(uint32_t saddr, const void* gptr) {
    asm volatile("cp.async.cg.shared.global [%0], [%1], 16;\n"
                 :: "r"(saddr), "l"(gptr) : "memory");
}

// ---------------------------------------------------------------------------
// Single-pass kernel: one (b, n-tile) per block. x read ONCE from DRAM.
// ---------------------------------------------------------------------------
__global__ __launch_bounds__(TPB)
void k_all(const float* __restrict__ x, float* __restrict__ z,
           const float* __restrict__ gw, const float* __restrict__ gb,
           const float* __restrict__ tw, const float* __restrict__ tb,
           const float* __restrict__ pw, const float* __restrict__ pb,
           const float* __restrict__ Ww, const float* __restrict__ Wb,
           const float* __restrict__ gamma, const float* __restrict__ beta,
           const float* __restrict__ mean,  const float* __restrict__ var)
{
    extern __shared__ float sm[];
    float* xs  = sm + OFF_X;
    float* pdg = sm + OFF_PD;          // [8][64]
    float* pdt = sm + OFF_PD + 512;
    float* pdp = sm + OFF_PD + 1024;
    float* sA  = sm + OFF_SA;          // alias (post-merge)
    float* sD  = sm + OFF_SD;          // alias (post-merge)
    float* sps = sm + OFF_SPS;         // alias (post-merge)
    float* red = sm + OFF_RED;         // alias (post-merge, disjoint)
    float* swg = sm + OFF_W;
    float* swt = sm + OFF_W + 256;
    float* swp = sm + OFF_W + 512;
    float* th  = sm + OFF_TH;

    const int bid  = blockIdx.x;
    const int b    = bid / NT;
    const int tile = bid - b * NT;
    const int n0   = tile * TILE;
    const int tid  = threadIdx.x;

    // ---- phase 1: issue ALL x-tile loads (cp.async, 8 x 16B per thread) ----
    const float* xg = x + (size_t)b * C_ * N_ + n0;
    {
        uint32_t sbase;
        asm("{ .reg .u64 t; cvta.to.shared.u64 t, %1; cvt.u32.u64 %0, t; }"
            : "=r"(sbase) : "l"(xs));
        #pragma unroll
        for (int k = 0; k < 8; k++) {
            const int chunk = k * TPB + tid;        // 0..4095
            const int c = chunk >> 4;
            const int j = chunk & 15;
            cp_async16(sbase + (uint32_t)(c * TILE + j * 4) * 4u,
                       xg + (size_t)c * N_ + j * 4);
        }
        asm volatile("cp.async.commit_group;\n" ::: "memory");
    }

    // ---- overlap: stage projection weights ----
    if (tid < C_) {
        swg[tid] = __ldg(gw + tid);
        swt[tid] = __ldg(tw + tid);
        swp[tid] = __ldg(pw + tid);
    }

    asm volatile("cp.async.wait_group 0;\n" ::: "memory");
    __syncthreads();

    // ---- phase 2: dots (thread = (n, c-eighth)) ----
    const int n = tid & (TILE - 1);
    const int g = tid >> 6;                 // 0..7
    {
        float ga = 0.f, ta = 0.f, pa = 0.f;
        const int cb = g * 32;
        #pragma unroll
        for (int cc = 0; cc < 32; cc++) {
            const int c = cb + cc;
            const float xv = xs[c * TILE + n];
            ga = fmaf(swg[c], xv, ga);
            ta = fmaf(swt[c], xv, ta);
            pa = fmaf(swp[c], xv, pa);
        }
        pdg[g * TILE + n] = ga;
        pdt[g * TILE + n] = ta;
        pdp[g * TILE + n] = pa;
    }
    __syncthreads();

    // ---- merge eighths, theta row, tile partial of sum(phi*g) ----
    if (tid < TILE) {
        float G = __ldg(gb), P = __ldg(pb), T = __ldg(tb);
        #pragma unroll
        for (int q = 0; q < 8; q++) {       // fixed order
            G += pdg[q * TILE + tid];
            P += pdp[q * TILE + tid];
            T += pdt[q * TILE + tid];
        }
        th[tid] = T;
        float pg = G * P;
        #pragma unroll
        for (int off = 16; off > 0; off >>= 1)
            pg += __shfl_xor_sync(0xffffffffu, pg, off);
        if ((tid & 31) == 0) red[tid >> 5] = pg;
    }
    __syncthreads();                        // pd region now dead (except red)

    // ---- publish + spin (thread 0) overlapped with BN-coef staging ----
    if (tid == 0) {
        g_sp[b * NT + tile] = red[0] + red[1];
        __threadfence();
        atomicAdd(&g_cnt[b * CPAD], 1u);
        // poll with plain volatile loads (no RMW serialization on release)
        const volatile unsigned* cp = (const volatile unsigned*)&g_cnt[b * CPAD];
        while (*cp < (unsigned)NT)
            __nanosleep(128);
        __threadfence();
    } else if (tid >= 64 && tid < 64 + C_) {
        const int c = tid - 64;
        const float inv = __ldg(gamma + c) * rsqrtf(__ldg(var + c) + 1e-5f);
        sA[c] = __ldg(Ww + c) * inv;
        sD[c] = (__ldg(Wb + c) - __ldg(mean + c)) * inv + __ldg(beta + c);
    }
    __syncthreads();

    // stage the 72 partials; every thread then sums in identical fixed order
    if (tid < NT) sps[tid] = g_sp[b * NT + tid];
    __syncthreads();
    float s = 0.f;
    #pragma unroll
    for (int t = 0; t < NT; t++) s += sps[t];
    s *= (1.f / (float)N_);

    // ---- phase 3: epilogue, all from smem: z = th*ca + cd + x ----
    {
        const float4* xs4 = reinterpret_cast<const float4*>(xs);
        const float4* th4 = reinterpret_cast<const float4*>(th);
        #pragma unroll
        for (int k = 0; k < 8; k++) {
            const int f = k * TPB + tid;        // 0..4095
            const int c = f >> 4;
            const int j = f & 15;
            const float ca = sA[c] * s;
            const float cd = sD[c];
            const float4 tv = th4[j];
            const float4 xv = xs4[c * 16 + j];
            float4 o;
            o.x = fmaf(tv.x, ca, cd) + xv.x;
            o.y = fmaf(tv.y, ca, cd) + xv.y;
            o.z = fmaf(tv.z, ca, cd) + xv.z;
            o.w = fmaf(tv.w, ca, cd) + xv.w;
            float4* zp = reinterpret_cast<float4*>(z + ((size_t)b * C_ + c) * N_ + n0) + j;
            __stcs(zp, o);
        }
    }

    // ---- self-reset counters for the next (graph-replayed) launch ----
    __syncthreads();
    if (tid == 0) {
        const unsigned old = atomicAdd(&g_done[b * CPAD], 1u);
        if (old == (unsigned)(NT - 1)) {
            g_cnt[b * CPAD]  = 0;
            g_done[b * CPAD] = 0;
            __threadfence();
        }
    }
}

// ---------------------------------------------------------------------------
extern "C" void kernel_launch(void* const* d_in, const int* in_sizes, int n_in,
                              void* d_out, int out_size)
{
    const float* x     = (const float*)d_in[0];
    const float* g_w   = (const float*)d_in[1];
    const float* g_b   = (const float*)d_in[2];
    const float* th_w  = (const float*)d_in[3];
    const float* th_b  = (const float*)d_in[4];
    const float* ph_w  = (const float*)d_in[5];
    const float* ph_b  = (const float*)d_in[6];
    const float* W_w   = (const float*)d_in[7];
    const float* W_b   = (const float*)d_in[8];
    const float* gamma = (const float*)d_in[9];
    const float* beta  = (const float*)d_in[10];
    const float* mean  = (const float*)d_in[11];
    const float* var   = (const float*)d_in[12];
    float* z = (float*)d_out;

    static bool attr_set = false;
    if (!attr_set) {
        cudaFuncSetAttribute(k_all, cudaFuncAttributeMaxDynamicSharedMemorySize, SMEM_B);
        attr_set = true;
    }

    k_all<<<B_ * NT, TPB, SMEM_B>>>(x, z, g_w, g_b, th_w, th_b, ph_w, ph_b,
                                    W_w, W_b, gamma, beta, mean, var);
}